// round 1
// baseline (speedup 1.0000x reference)
#include <cuda_runtime.h>
#include <math.h>

#define NSAMP 4096
#define NV    65536
#define DIM   128
#define EPSF  1e-6f

#define GX 64              // V-split blocks (each handles 8 tiles of 128 rows)
#define GY 32              // sample tiles of 128
#define TILES_PER_BLOCK 8
#define BN 128
#define BM 128

#define SMEM_BYTES ((128*128 + 2*16*128 + 128*16*2 + 128*16*2) * 4)  // 114688

__device__ float d_c[NV];
__device__ float d_pval[GX * NSAMP * 2];
__device__ int   d_pidx[GX * NSAMP * 2];

#define BIGF 3.402823466e38f

__device__ __forceinline__ void upd2(float v, int i, float& v1, int& i1, float& v2, int& i2) {
    bool b1 = (v < v1) || (v == v1 && i < i1);
    if (b1) { v2 = v1; i2 = i1; v1 = v; i1 = i; }
    else if ((v < v2) || (v == v2 && i < i2)) { v2 = v; i2 = i; }
}

// ---------------- kernel 0: per-codeword constant c[n] = |v|^2 - 2*eps*sum(v)
__global__ void __launch_bounds__(256) prep_kernel(const float* __restrict__ V) {
    int row = blockIdx.x * 8 + (threadIdx.x >> 5);
    int l = threadIdx.x & 31;
    float4 v = ((const float4*)V)[(size_t)row * 32 + l];
    float sq = v.x*v.x + v.y*v.y + v.z*v.z + v.w*v.w;
    float sm = v.x + v.y + v.z + v.w;
    #pragma unroll
    for (int o = 16; o > 0; o >>= 1) {
        sq += __shfl_down_sync(0xffffffffu, sq, o);
        sm += __shfl_down_sync(0xffffffffu, sm, o);
    }
    if (l == 0) d_c[row] = sq - 2.0f * EPSF * sm;
}

#define FMA2(acc_, a_, b_) \
    asm("fma.rn.f32x2 %0, %1, %2, %3;" : "=l"(acc_) : "l"(a_), "l"(b_), "l"(acc_))
#define DUP2(d_, f_) \
    asm("mov.b64 %0, {%1, %1};" : "=l"(d_) : "r"(__float_as_uint(f_)))

// ---------------- kernel 1: GEMM score + per-block top-2
__global__ void __launch_bounds__(256, 2) main_kernel(const float* __restrict__ S,
                                                      const float* __restrict__ V) {
    extern __shared__ float smem[];
    float* As = smem;                       // [128 k][128 m], k-major
    float* Bs = smem + 128 * 128;           // [2][16 k][128 n]
    float* Rv = Bs + 2 * 16 * 128;          // [128 sample][16 tx][2]
    int*   Ri = (int*)(Rv + 128 * 16 * 2);

    const int tid = threadIdx.x;
    const int l = tid & 31, w = tid >> 5;
    const int tx = tid & 15, ty = tid >> 4;
    const int m0 = blockIdx.y * BM;
    const long nbase = (long)blockIdx.x * (BN * TILES_PER_BLOCK);

    // load + transpose sample tile into k-major smem (once per block)
    {
        const float4* S4 = (const float4*)S;
        #pragma unroll
        for (int g = 0; g < 4; g++) {
            int m = g * 32 + l;
            #pragma unroll
            for (int q = 0; q < 4; q++) {
                int kq = w * 4 + q;
                float4 a = S4[(size_t)(m0 + m) * 32 + kq];
                As[(kq*4 + 0) * BM + m] = a.x;
                As[(kq*4 + 1) * BM + m] = a.y;
                As[(kq*4 + 2) * BM + m] = a.z;
                As[(kq*4 + 3) * BM + m] = a.w;
            }
        }
    }

    float gv1 = BIGF, gv2 = BIGF;
    int   gi1 = 0x7fffffff, gi2 = 0x7fffffff;

    const float4* V4 = (const float4*)V;
    const int brow = ((w & 3) << 5) + l;    // 0..127
    const int bkq  = (w >> 2) << 1;         // 0 or 2 (float4-quad within chunk)

    for (int t = 0; t < TILES_PER_BLOCK; t++) {
        const long n0 = nbase + (long)t * BN;

        unsigned long long acc[8][4];
        #pragma unroll
        for (int i = 0; i < 8; i++)
            #pragma unroll
            for (int j = 0; j < 4; j++) acc[i][j] = 0ull;

        // stage chunk 0 into buffer 0
        {
            float4 p0 = V4[(size_t)(n0 + brow) * 32 + bkq + 0];
            float4 p1 = V4[(size_t)(n0 + brow) * 32 + bkq + 1];
            float* Bd = Bs;
            Bd[((bkq+0)*4 + 0)*BN + brow] = p0.x;
            Bd[((bkq+0)*4 + 1)*BN + brow] = p0.y;
            Bd[((bkq+0)*4 + 2)*BN + brow] = p0.z;
            Bd[((bkq+0)*4 + 3)*BN + brow] = p0.w;
            Bd[((bkq+1)*4 + 0)*BN + brow] = p1.x;
            Bd[((bkq+1)*4 + 1)*BN + brow] = p1.y;
            Bd[((bkq+1)*4 + 2)*BN + brow] = p1.z;
            Bd[((bkq+1)*4 + 3)*BN + brow] = p1.w;
        }
        __syncthreads();

        int buf = 0;
        #pragma unroll 1
        for (int kc = 0; kc < 8; kc++) {
            float4 p0, p1;
            if (kc < 7) {
                p0 = V4[(size_t)(n0 + brow) * 32 + (kc+1)*4 + bkq + 0];
                p1 = V4[(size_t)(n0 + brow) * 32 + (kc+1)*4 + bkq + 1];
            }
            const float* Bp = Bs + buf * (16 * BN);
            #pragma unroll 4
            for (int kk = 0; kk < 16; kk++) {
                const float* Ap = As + (kc*16 + kk) * BM;
                float4 a0 = *(const float4*)(Ap + ty*4);
                float4 a1 = *(const float4*)(Ap + 64 + ty*4);
                const float* Bk = Bp + kk * BN;
                ulonglong2 b0 = *(const ulonglong2*)(Bk + tx*4);
                ulonglong2 b1 = *(const ulonglong2*)(Bk + 64 + tx*4);
                unsigned long long ad[8];
                DUP2(ad[0], a0.x); DUP2(ad[1], a0.y);
                DUP2(ad[2], a0.z); DUP2(ad[3], a0.w);
                DUP2(ad[4], a1.x); DUP2(ad[5], a1.y);
                DUP2(ad[6], a1.z); DUP2(ad[7], a1.w);
                #pragma unroll
                for (int i = 0; i < 8; i++) {
                    FMA2(acc[i][0], ad[i], b0.x);
                    FMA2(acc[i][1], ad[i], b0.y);
                    FMA2(acc[i][2], ad[i], b1.x);
                    FMA2(acc[i][3], ad[i], b1.y);
                }
            }
            if (kc < 7) {
                float* Bd = Bs + (buf ^ 1) * (16 * BN);
                Bd[((bkq+0)*4 + 0)*BN + brow] = p0.x;
                Bd[((bkq+0)*4 + 1)*BN + brow] = p0.y;
                Bd[((bkq+0)*4 + 2)*BN + brow] = p0.z;
                Bd[((bkq+0)*4 + 3)*BN + brow] = p0.w;
                Bd[((bkq+1)*4 + 0)*BN + brow] = p1.x;
                Bd[((bkq+1)*4 + 1)*BN + brow] = p1.y;
                Bd[((bkq+1)*4 + 2)*BN + brow] = p1.z;
                Bd[((bkq+1)*4 + 3)*BN + brow] = p1.w;
            }
            __syncthreads();
            buf ^= 1;
        }

        // epilogue: score = c[n] - 2*dot, per-thread top-2, block reduce
        float4 c0 = *(const float4*)(d_c + n0 + tx*4);
        float4 c1 = *(const float4*)(d_c + n0 + 64 + tx*4);
        float cv[8] = {c0.x, c0.y, c0.z, c0.w, c1.x, c1.y, c1.z, c1.w};
        #pragma unroll
        for (int i = 0; i < 8; i++) {
            float v1 = BIGF, v2 = BIGF;
            int   i1 = 0x7fffffff, i2 = 0x7fffffff;
            #pragma unroll
            for (int jp = 0; jp < 4; jp++) {
                unsigned long long pa = acc[i][jp];
                float lo = __uint_as_float((unsigned)pa);
                float hi = __uint_as_float((unsigned)(pa >> 32));
                int jl = (jp < 2) ? (jp*2) : (4 + (jp-2)*2);
                int nloc = (jp < 2) ? (tx*4 + jp*2) : (64 + tx*4 + (jp-2)*2);
                float s0 = cv[jl]   - 2.0f * lo;
                float s1 = cv[jl+1] - 2.0f * hi;
                int idx0 = (int)n0 + nloc;
                upd2(s0, idx0,     v1, i1, v2, i2);
                upd2(s1, idx0 + 1, v1, i1, v2, i2);
            }
            int sl = (i < 4) ? (ty*4 + i) : (64 + ty*4 + (i - 4));
            int off = (sl*16 + tx)*2;
            Rv[off]     = v1; Ri[off]     = i1;
            Rv[off + 1] = v2; Ri[off + 1] = i2;
        }
        __syncthreads();
        if (tid < 128) {
            #pragma unroll
            for (int u = 0; u < 32; u++) {
                float v = Rv[tid*32 + u];
                int   i = Ri[tid*32 + u];
                upd2(v, i, gv1, gi1, gv2, gi2);
            }
        }
        // Rv/Ri are rewritten only after many __syncthreads in the next tile
    }

    if (tid < 128) {
        size_t o = ((size_t)blockIdx.x * NSAMP + (m0 + tid)) * 2;
        d_pval[o]     = gv1; d_pidx[o]     = gi1;
        d_pval[o + 1] = gv2; d_pidx[o + 1] = gi2;
    }
}

// ---------------- kernel 2: merge partials, finalize outputs
__global__ void __launch_bounds__(256) merge_kernel(const float* __restrict__ S,
                                                    float* __restrict__ out) {
    int s = blockIdx.x * 256 + threadIdx.x;
    float v1 = BIGF, v2 = BIGF;
    int   i1 = 0x7fffffff, i2 = 0x7fffffff;
    for (int g = 0; g < GX; g++) {
        size_t o = ((size_t)g * NSAMP + s) * 2;
        upd2(d_pval[o],     d_pidx[o],     v1, i1, v2, i2);
        upd2(d_pval[o + 1], d_pidx[o + 1], v1, i1, v2, i2);
    }
    float xsq = 0.f, xsm = 0.f;
    const float4* S4 = (const float4*)S;
    #pragma unroll
    for (int q = 0; q < 32; q++) {
        float4 x = S4[(size_t)s * 32 + q];
        xsq += x.x*x.x + x.y*x.y + x.z*x.z + x.w*x.w;
        xsm += x.x + x.y + x.z + x.w;
    }
    float xc = xsq + 2.0f * EPSF * xsm + (float)DIM * EPSF * EPSF;
    float dist = sqrtf(fmaxf(xc + v1, 0.0f));
    out[s]             = (float)i1;       // b
    out[NSAMP + s]     = (float)i2;       // s
    out[2*NSAMP + s]   = expf(-dist);     // a
}

extern "C" void kernel_launch(void* const* d_in, const int* in_sizes, int n_in,
                              void* d_out, int out_size) {
    const float* S = (const float*)d_in[0];   // samples [4096,128]
    const float* V = (const float*)d_in[1];   // V [65536,128]
    float* out = (float*)d_out;

    cudaFuncSetAttribute(main_kernel, cudaFuncAttributeMaxDynamicSharedMemorySize, SMEM_BYTES);

    prep_kernel<<<NV / 8, 256>>>(V);
    main_kernel<<<dim3(GX, GY), 256, SMEM_BYTES>>>(S, V);
    merge_kernel<<<NSAMP / 256, 256>>>(S, out);
}

// round 4
// speedup vs baseline: 1.0614x; 1.0614x over previous
#include <cuda_runtime.h>
#include <math.h>

#define NSAMP 4096
#define NV    65536
#define DIM   128
#define EPSF  1e-6f

#define GX 64
#define GY 32
#define TILES_PER_BLOCK 8
#define BN 128
#define BM 128

// As 128x128 + Bs 2x16x128 + tmv 128x17 + thr 128 + cnt 128 + candV 128x16 + candI 128x16
#define SMEM_WORDS (128*128 + 2*16*128 + 128*17 + 128 + 128 + 128*16 + 128*16)
#define SMEM_BYTES (SMEM_WORDS * 4)   // 108032

__device__ float d_c[NV];
__device__ float d_pval[GX * NSAMP * 2];
__device__ int   d_pidx[GX * NSAMP * 2];

#define BIGF 3.402823466e38f

__device__ __forceinline__ void upd2(float v, int i, float& v1, int& i1, float& v2, int& i2) {
    bool b1 = (v < v1) || (v == v1 && i < i1);
    if (b1) { v2 = v1; i2 = i1; v1 = v; i1 = i; }
    else if ((v < v2) || (v == v2 && i < i2)) { v2 = v; i2 = i; }
}

// ---------------- kernel 0: per-codeword constant c[n] = |v|^2 - 2*eps*sum(v)
__global__ void __launch_bounds__(256) prep_kernel(const float* __restrict__ V) {
    int row = blockIdx.x * 8 + (threadIdx.x >> 5);
    int l = threadIdx.x & 31;
    float4 v = ((const float4*)V)[(size_t)row * 32 + l];
    float sq = v.x*v.x + v.y*v.y + v.z*v.z + v.w*v.w;
    float sm = v.x + v.y + v.z + v.w;
    #pragma unroll
    for (int o = 16; o > 0; o >>= 1) {
        sq += __shfl_down_sync(0xffffffffu, sq, o);
        sm += __shfl_down_sync(0xffffffffu, sm, o);
    }
    if (l == 0) d_c[row] = sq - 2.0f * EPSF * sm;
}

#define FMA2(acc_, a_, b_) \
    asm("fma.rn.f32x2 %0, %1, %2, %3;" : "=l"(acc_) : "l"(a_), "l"(b_), "l"(acc_))
#define SC2(d_, a_, b_, c_) \
    asm("fma.rn.f32x2 %0, %1, %2, %3;" : "=l"(d_) : "l"(a_), "l"(b_), "l"(c_))
#define DUP2(d_, f_) \
    asm("mov.b64 %0, {%1, %1};" : "=l"(d_) : "r"(__float_as_uint(f_)))
#define UNPK(lo_, hi_, v_) \
    asm("mov.b64 {%0, %1}, %2;" : "=r"(lo_), "=r"(hi_) : "l"(v_))

__device__ __forceinline__ float min2f(unsigned long long p) {
    unsigned lo_u, hi_u;
    UNPK(lo_u, hi_u, p);
    return fminf(__uint_as_float(lo_u), __uint_as_float(hi_u));
}

// ---------------- kernel 1: GEMM score + filtered top-2
__global__ void __launch_bounds__(256, 2) main_kernel(const float* __restrict__ S,
                                                      const float* __restrict__ V) {
    extern __shared__ float smem[];
    float* As  = smem;                         // [128 k][128 m], k-major
    float* Bs  = As + 128 * 128;               // [2][16 k][128 n]
    float* tmv = Bs + 2 * 16 * 128;            // [128 row][17] thread mins (padded)
    float* thr = tmv + 128 * 17;               // [128] capture threshold
    int*   cnt = (int*)(thr + 128);            // [128] candidate counters
    float* cV  = (float*)(cnt + 128);          // [128][16]
    int*   cI  = (int*)(cV + 128 * 16);        // [128][16]

    const int tid = threadIdx.x;
    const int l = tid & 31, w = tid >> 5;
    const int tx = tid & 15, ty = tid >> 4;
    const int m0 = blockIdx.y * BM;
    const long nbase = (long)blockIdx.x * (BN * TILES_PER_BLOCK);

    // load + transpose sample tile into k-major smem (once per block)
    {
        const float4* S4 = (const float4*)S;
        #pragma unroll
        for (int g = 0; g < 4; g++) {
            int m = g * 32 + l;
            #pragma unroll
            for (int q = 0; q < 4; q++) {
                int kq = w * 4 + q;
                float4 a = S4[(size_t)(m0 + m) * 32 + kq];
                As[(kq*4 + 0) * BM + m] = a.x;
                As[(kq*4 + 1) * BM + m] = a.y;
                As[(kq*4 + 2) * BM + m] = a.z;
                As[(kq*4 + 3) * BM + m] = a.w;
            }
        }
    }

    // running exact per-row top-2, held by row owners (tid < 128, row = tid)
    float rv1 = BIGF, rv2 = BIGF;
    int   ri1 = 0x7fffffff, ri2 = 0x7fffffff;

    const float4* V4 = (const float4*)V;
    const int brow = ((w & 3) << 5) + l;
    const int bkq  = (w >> 2) << 1;

    unsigned long long neg2;
    DUP2(neg2, -2.0f);

    for (int t = 0; t < TILES_PER_BLOCK; t++) {
        const long n0 = nbase + (long)t * BN;

        unsigned long long acc[8][4];
        #pragma unroll
        for (int i = 0; i < 8; i++)
            #pragma unroll
            for (int j = 0; j < 4; j++) acc[i][j] = 0ull;

        // stage chunk 0 into buffer 0
        {
            float4 p0 = V4[(size_t)(n0 + brow) * 32 + bkq + 0];
            float4 p1 = V4[(size_t)(n0 + brow) * 32 + bkq + 1];
            float* Bd = Bs;
            Bd[((bkq+0)*4 + 0)*BN + brow] = p0.x;
            Bd[((bkq+0)*4 + 1)*BN + brow] = p0.y;
            Bd[((bkq+0)*4 + 2)*BN + brow] = p0.z;
            Bd[((bkq+0)*4 + 3)*BN + brow] = p0.w;
            Bd[((bkq+1)*4 + 0)*BN + brow] = p1.x;
            Bd[((bkq+1)*4 + 1)*BN + brow] = p1.y;
            Bd[((bkq+1)*4 + 2)*BN + brow] = p1.z;
            Bd[((bkq+1)*4 + 3)*BN + brow] = p1.w;
        }
        __syncthreads();

        int buf = 0;
        #pragma unroll 1
        for (int kc = 0; kc < 8; kc++) {
            float4 p0, p1;
            if (kc < 7) {
                p0 = V4[(size_t)(n0 + brow) * 32 + (kc+1)*4 + bkq + 0];
                p1 = V4[(size_t)(n0 + brow) * 32 + (kc+1)*4 + bkq + 1];
            }
            const float* Bp = Bs + buf * (16 * BN);
            #pragma unroll 4
            for (int kk = 0; kk < 16; kk++) {
                const float* Ap = As + (kc*16 + kk) * BM;
                float4 a0 = *(const float4*)(Ap + ty*4);
                float4 a1 = *(const float4*)(Ap + 64 + ty*4);
                const float* Bk = Bp + kk * BN;
                ulonglong2 b0 = *(const ulonglong2*)(Bk + tx*4);
                ulonglong2 b1 = *(const ulonglong2*)(Bk + 64 + tx*4);
                unsigned long long ad[8];
                DUP2(ad[0], a0.x); DUP2(ad[1], a0.y);
                DUP2(ad[2], a0.z); DUP2(ad[3], a0.w);
                DUP2(ad[4], a1.x); DUP2(ad[5], a1.y);
                DUP2(ad[6], a1.z); DUP2(ad[7], a1.w);
                #pragma unroll
                for (int i = 0; i < 8; i++) {
                    FMA2(acc[i][0], ad[i], b0.x);
                    FMA2(acc[i][1], ad[i], b0.y);
                    FMA2(acc[i][2], ad[i], b1.x);
                    FMA2(acc[i][3], ad[i], b1.y);
                }
            }
            if (kc < 7) {
                float* Bd = Bs + (buf ^ 1) * (16 * BN);
                Bd[((bkq+0)*4 + 0)*BN + brow] = p0.x;
                Bd[((bkq+0)*4 + 1)*BN + brow] = p0.y;
                Bd[((bkq+0)*4 + 2)*BN + brow] = p0.z;
                Bd[((bkq+0)*4 + 3)*BN + brow] = p0.w;
                Bd[((bkq+1)*4 + 0)*BN + brow] = p1.x;
                Bd[((bkq+1)*4 + 1)*BN + brow] = p1.y;
                Bd[((bkq+1)*4 + 2)*BN + brow] = p1.z;
                Bd[((bkq+1)*4 + 3)*BN + brow] = p1.w;
            }
            __syncthreads();
            buf ^= 1;
        }

        // ---- epilogue: packed scores + scalar-min filter ----
        ulonglong2 cp0 = *(const ulonglong2*)(d_c + n0 + tx*4);
        ulonglong2 cp1 = *(const ulonglong2*)(d_c + n0 + 64 + tx*4);
        float mrow[8];
        #pragma unroll
        for (int i = 0; i < 8; i++) {
            SC2(acc[i][0], acc[i][0], neg2, cp0.x);
            SC2(acc[i][1], acc[i][1], neg2, cp0.y);
            SC2(acc[i][2], acc[i][2], neg2, cp1.x);
            SC2(acc[i][3], acc[i][3], neg2, cp1.y);
            float m = fminf(fminf(min2f(acc[i][0]), min2f(acc[i][1])),
                            fminf(min2f(acc[i][2]), min2f(acc[i][3])));
            mrow[i] = m;
            int r = (i < 4) ? (ty*4 + i) : (64 + ty*4 + (i - 4));
            tmv[r*17 + tx] = m;
        }
        __syncthreads();

        // row owners: compute capture threshold T >= true current V2, reset counters
        if (tid < 128) {
            float m1 = BIGF, m2 = BIGF;
            #pragma unroll
            for (int u = 0; u < 16; u++) {
                float x = tmv[tid*17 + u];
                m2 = fminf(m2, fmaxf(m1, x));
                m1 = fminf(m1, x);
            }
            float T = fminf(fmaxf(rv1, m1), fminf(rv2, m2));
            thr[tid] = T;
            cnt[tid] = 0;
        }
        __syncthreads();

        // push phase: rare candidates only
        int mask = 0;
        float Trow[8];
        #pragma unroll
        for (int i = 0; i < 8; i++) {
            int r = (i < 4) ? (ty*4 + i) : (64 + ty*4 + (i - 4));
            float T = thr[r];
            Trow[i] = T;
            if (mrow[i] <= T) mask |= (1 << i);
        }
        if (mask) {
            #pragma unroll
            for (int i = 0; i < 8; i++) if (mask & (1 << i)) {
                int r = (i < 4) ? (ty*4 + i) : (64 + ty*4 + (i - 4));
                float T = Trow[i];
                #pragma unroll
                for (int j = 0; j < 4; j++) {
                    unsigned lo_u, hi_u;
                    UNPK(lo_u, hi_u, acc[i][j]);
                    float s0 = __uint_as_float(lo_u);
                    float s1 = __uint_as_float(hi_u);
                    int idx0 = (int)n0 + ((j < 2) ? (tx*4 + j*2) : (64 + tx*4 + (j-2)*2));
                    if (s0 <= T) {
                        int p = atomicAdd(&cnt[r], 1);
                        if (p < 16) { cV[r*16 + p] = s0; cI[r*16 + p] = idx0; }
                    }
                    if (s1 <= T) {
                        int p = atomicAdd(&cnt[r], 1);
                        if (p < 16) { cV[r*16 + p] = s1; cI[r*16 + p] = idx0 + 1; }
                    }
                }
            }
        }
        __syncthreads();

        // row owners merge candidates exactly (index-aware tie-break)
        if (tid < 128) {
            int K = cnt[tid]; if (K > 16) K = 16;
            for (int k = 0; k < K; k++)
                upd2(cV[tid*16 + k], cI[tid*16 + k], rv1, ri1, rv2, ri2);
        }
        // next tile's writes to tmv/cnt/cV happen only after 2+ syncthreads
    }

    if (tid < 128) {
        size_t o = ((size_t)blockIdx.x * NSAMP + (m0 + tid)) * 2;
        d_pval[o]     = rv1; d_pidx[o]     = ri1;
        d_pval[o + 1] = rv2; d_pidx[o + 1] = ri2;
    }
}

// ---------------- kernel 2: merge partials, finalize outputs
__global__ void __launch_bounds__(256) merge_kernel(const float* __restrict__ S,
                                                    float* __restrict__ out) {
    int s = blockIdx.x * 256 + threadIdx.x;
    float v1 = BIGF, v2 = BIGF;
    int   i1 = 0x7fffffff, i2 = 0x7fffffff;
    for (int g = 0; g < GX; g++) {
        size_t o = ((size_t)g * NSAMP + s) * 2;
        upd2(d_pval[o],     d_pidx[o],     v1, i1, v2, i2);
        upd2(d_pval[o + 1], d_pidx[o + 1], v1, i1, v2, i2);
    }
    float xsq = 0.f, xsm = 0.f;
    const float4* S4 = (const float4*)S;
    #pragma unroll
    for (int q = 0; q < 32; q++) {
        float4 x = S4[(size_t)s * 32 + q];
        xsq += x.x*x.x + x.y*x.y + x.z*x.z + x.w*x.w;
        xsm += x.x + x.y + x.z + x.w;
    }
    float xc = xsq + 2.0f * EPSF * xsm + (float)DIM * EPSF * EPSF;
    float dist = sqrtf(fmaxf(xc + v1, 0.0f));
    out[s]             = (float)i1;       // b
    out[NSAMP + s]     = (float)i2;       // s
    out[2*NSAMP + s]   = expf(-dist);     // a
}

extern "C" void kernel_launch(void* const* d_in, const int* in_sizes, int n_in,
                              void* d_out, int out_size) {
    const float* S = (const float*)d_in[0];   // samples [4096,128]
    const float* V = (const float*)d_in[1];   // V [65536,128]
    float* out = (float*)d_out;

    cudaFuncSetAttribute(main_kernel, cudaFuncAttributeMaxDynamicSharedMemorySize, SMEM_BYTES);

    prep_kernel<<<NV / 8, 256>>>(V);
    main_kernel<<<dim3(GX, GY), 256, SMEM_BYTES>>>(S, V);
    merge_kernel<<<NSAMP / 256, 256>>>(S, out);
}